// round 9
// baseline (speedup 1.0000x reference)
#include <cuda_runtime.h>
#include <cuda_bf16.h>

#define H 1024
#define L 50
#define V 50257
#define NBLK ((V + 7) / 8)   // 6283 blocks for the big matvec
#define REP 32               // vector replication factor (L2-slice spreading)

// ---------------- scratch (device globals; no allocation allowed) ----------
__device__ float g_emb[H];          // embedded row
__device__ float g_scores[L];       // attention logits
__device__ float g_cat2[2 * H];     // [embedded | attn_applied]
__device__ float g_vecR[REP][H];    // comb output, replicated
__device__ float g_h0R[REP][H];     // initial hidden, replicated
__device__ float g_h1R[REP][H];     // h after cell 1, replicated
__device__ float g_h2R[REP][H];     // h after cell 2, replicated
__device__ float g_dp[4 * 6 * H];   // quarter-row gate partials [q][c][i]
__device__ float g_pm[NBLK + 64];   // per-block partial max
__device__ float g_ps[NBLK + 64];   // per-block partial sum-exp
__device__ float g_lse;

// ---------------- K0: attention scores (one block per l) -------------------
__global__ void __launch_bounds__(256)
k_scores(const int* __restrict__ ids,
         const float* __restrict__ hidden,
         const float* __restrict__ emb,
         const float* __restrict__ attn_w,
         const float* __restrict__ attn_b) {
    int l = blockIdx.x;
    int row = ids[0];
    const float* er = emb + (size_t)row * H;

    if (l == 0) {
        for (int i = threadIdx.x; i < H; i += blockDim.x) {
            g_emb[i] = er[i];
            float h = hidden[i];
            #pragma unroll
            for (int rp = 0; rp < REP; rp++) g_h0R[rp][i] = h;
        }
    }

    const float* w = attn_w + (size_t)l * 2 * H;
    float acc = 0.f;
    for (int j = threadIdx.x; j < H; j += blockDim.x)
        acc += w[j] * er[j] + w[H + j] * hidden[j];

    __shared__ float red[8];
    #pragma unroll
    for (int o = 16; o; o >>= 1) acc += __shfl_down_sync(0xffffffffu, acc, o);
    if ((threadIdx.x & 31) == 0) red[threadIdx.x >> 5] = acc;
    __syncthreads();
    if (threadIdx.x < 8) {
        float v = red[threadIdx.x];
        #pragma unroll
        for (int o = 4; o; o >>= 1) v += __shfl_down_sync(0xffu, v, o);
        if (threadIdx.x == 0) g_scores[l] = v + attn_b[l];
    }
}

// ---------------- K1: softmax + attn_applied + concat (8 blocks) -----------
__global__ void __launch_bounds__(128)
k_attn(const float* __restrict__ enc, float* __restrict__ out) {
    __shared__ float aw[64];
    int t = threadIdx.x;
    if (t < 64) aw[t] = (t < L) ? g_scores[t] : -1e30f;
    __syncthreads();
    if (t < 32) {
        float a = aw[t], b = aw[t + 32];
        float m = fmaxf(a, b);
        #pragma unroll
        for (int o = 16; o; o >>= 1) m = fmaxf(m, __shfl_xor_sync(0xffffffffu, m, o));
        float e1 = (t < L) ? __expf(a - m) : 0.f;
        float e2 = (t + 32 < L) ? __expf(b - m) : 0.f;
        float s = e1 + e2;
        #pragma unroll
        for (int o = 16; o; o >>= 1) s += __shfl_xor_sync(0xffffffffu, s, o);
        float inv = 1.f / s;
        aw[t] = e1 * inv;
        aw[t + 32] = e2 * inv;
    }
    __syncthreads();
    if (blockIdx.x == 0 && t < L) out[V + H + t] = aw[t];   // attn_weights
    int i = blockIdx.x * 128 + t;                           // column slice
    float acc = 0.f;
    #pragma unroll 10
    for (int l = 0; l < L; l++) acc += aw[l] * enc[l * H + i];
    g_cat2[H + i] = acc;
    g_cat2[i] = g_emb[i];
}

// ---------------- K2: comb matvec (2 warps per row, grid=256) --------------
__global__ void __launch_bounds__(256)
k_comb(const float* __restrict__ comb_w,
       const float* __restrict__ comb_b) {
    __shared__ float sc[2 * H];
    __shared__ float part[8];
    __shared__ float vout[4];
    for (int i = threadIdx.x; i < 2 * H; i += 256) sc[i] = g_cat2[i];
    __syncthreads();
    int warp = threadIdx.x >> 5, lane = threadIdx.x & 31;
    int row = blockIdx.x * 4 + (warp >> 1);
    int half = warp & 1;
    const float4* w = (const float4*)(comb_w + (size_t)row * 2 * H + half * H);
    float acc = 0.f;
    #pragma unroll
    for (int k = 0; k < 8; k++) {
        int m = lane + k * 32;
        float4 a = w[m];
        int j = half * H + m * 4;
        acc += a.x * sc[j] + a.y * sc[j + 1] + a.z * sc[j + 2] + a.w * sc[j + 3];
    }
    #pragma unroll
    for (int o = 16; o; o >>= 1) acc += __shfl_down_sync(0xffffffffu, acc, o);
    if (lane == 0) part[warp] = acc;
    __syncthreads();
    if (threadIdx.x < 4)
        vout[threadIdx.x] = part[2 * threadIdx.x] + part[2 * threadIdx.x + 1]
                          + comb_b[blockIdx.x * 4 + threadIdx.x];
    __syncthreads();
    if (threadIdx.x < 4 * REP) {
        int rp = threadIdx.x >> 2, r = threadIdx.x & 3;
        g_vecR[rp][blockIdx.x * 4 + r] = vout[r];
    }
}

// ---------------- K3: GRU gate quarter-dots --------------------------------
// One warp per (matrix, gate, row, quarter): 24576 warps / 3072 blocks.
// c is block-uniform -> stage only the needed vector, from a replica.
__global__ void __launch_bounds__(256)
k_gates(const float* __restrict__ w_ih, const float* __restrict__ w_hh,
        int cell) {
    __shared__ float sv[H];
    int warp = threadIdx.x >> 5, lane = threadIdx.x & 31;
    int id = blockIdx.x * 8 + warp;          // 0..24575
    int q = id & 3;                          // quarter of the row
    int i = (id >> 2) & (H - 1);             // output row
    int c = id >> 12;                        // 0..5 (uniform within block)
    int gate = c >> 1;
    const float* wmat = (c & 1) ? w_hh : w_ih;
    const float4* w = (const float4*)(wmat + (size_t)(gate * H + i) * H) + q * 64;

    // 2 front-batched LDG.128
    float4 r0 = w[lane];
    float4 r1 = w[lane + 32];

    // stage the one vector this block needs, from a spread replica
    {
        int rp = blockIdx.x & (REP - 1);
        int cb = (blockIdx.x * 8) >> 12;
        const float* src = (cb & 1)
            ? ((cell == 0) ? g_h0R[rp] : g_h1R[rp])     // h side
            : ((cell == 0) ? g_vecR[rp] : g_h1R[rp]);   // x side (needs relu)
        bool rl = !(cb & 1);
        for (int t = threadIdx.x; t < H; t += 256) {
            float v = src[t];
            sv[t] = rl ? fmaxf(v, 0.f) : v;
        }
    }
    __syncthreads();
    const float* vec = sv + q * 256;

    int j0 = lane * 4, j1 = (lane + 32) * 4;
    float acc = r0.x * vec[j0] + r0.y * vec[j0 + 1] + r0.z * vec[j0 + 2] + r0.w * vec[j0 + 3]
              + r1.x * vec[j1] + r1.y * vec[j1 + 1] + r1.z * vec[j1 + 2] + r1.w * vec[j1 + 3];
    #pragma unroll
    for (int o = 16; o; o >>= 1) acc += __shfl_down_sync(0xffffffffu, acc, o);
    if (lane == 0) g_dp[q * 6 * H + c * H + i] = acc;
}

// ---------------- K4: GRU combine: sum quarters + biases + nonlinearity ----
__global__ void __launch_bounds__(128)
k_combine(const float* __restrict__ b_ih, const float* __restrict__ b_hh,
          float* __restrict__ out, int cell) {
    int i = blockIdx.x * 128 + threadIdx.x;
    float hold = (cell == 0) ? g_h0R[0][i] : g_h1R[0][i];
    float d[6];
    #pragma unroll
    for (int c = 0; c < 6; c++) {
        float s = 0.f;
        #pragma unroll
        for (int q = 0; q < 4; q++) s += g_dp[q * 6 * H + c * H + i];
        int gate = c >> 1;
        s += (c & 1) ? b_hh[gate * H + i] : b_ih[gate * H + i];
        d[c] = s;
    }
    float r = 1.f / (1.f + __expf(-(d[0] + d[1])));
    float z = 1.f / (1.f + __expf(-(d[2] + d[3])));
    float n = tanhf(d[4] + r * d[5]);
    float h = (1.f - z) * n + z * hold;
    if (cell == 0) {
        #pragma unroll
        for (int rp = 0; rp < REP; rp++) g_h1R[rp][i] = h;
    } else {
        #pragma unroll
        for (int rp = 0; rp < REP; rp++) g_h2R[rp][i] = h;
        out[V + i] = h;                 // hidden output
    }
}

// ---------------- K5: big matvec out_w @ h + partial logsumexp -------------
__global__ void __launch_bounds__(256)
k_out(const float* __restrict__ out_w,
      const float* __restrict__ out_b,
      float* __restrict__ out) {
    __shared__ float sv[H];
    __shared__ float sm[8];
    {
        const float* src = g_h2R[blockIdx.x & (REP - 1)];
        for (int i = threadIdx.x; i < H; i += 256) sv[i] = src[i];
    }
    __syncthreads();
    int warp = threadIdx.x >> 5, lane = threadIdx.x & 31;
    int row = blockIdx.x * 8 + warp;
    float logit = -1e30f;
    if (row < V) {
        const float4* w = (const float4*)(out_w + (size_t)row * H);
        float acc = 0.f;
        #pragma unroll
        for (int k = 0; k < 8; k++) {
            int m = lane + k * 32;
            float4 a = __ldcs(w + m);       // stream: don't pollute L2
            int j = m * 4;
            acc += a.x * sv[j] + a.y * sv[j + 1] + a.z * sv[j + 2] + a.w * sv[j + 3];
        }
        #pragma unroll
        for (int o = 16; o; o >>= 1) acc += __shfl_down_sync(0xffffffffu, acc, o);
        if (lane == 0) {
            logit = acc + out_b[row];
            out[row] = logit;
        }
    }
    if (lane == 0) sm[warp] = logit;
    __syncthreads();
    if (threadIdx.x == 0) {
        float m = -1e30f;
        #pragma unroll
        for (int k = 0; k < 8; k++) m = fmaxf(m, sm[k]);
        float s = 0.f;
        #pragma unroll
        for (int k = 0; k < 8; k++) s += __expf(sm[k] - m);
        g_pm[blockIdx.x] = m;
        g_ps[blockIdx.x] = s;
    }
}

// ---------------- K6: combine partials -> lse ------------------------------
__global__ void __launch_bounds__(256)
k_lse() {
    int t = threadIdx.x;
    float m = -1e30f, s = 0.f;
    for (int b = t; b < NBLK; b += 256) {
        float bm = g_pm[b], bs = g_ps[b];
        if (bm > m) { s = s * __expf(m - bm) + bs; m = bm; }
        else        { s += bs * __expf(bm - m); }
    }
    __shared__ float rm[8], rs[8];
    #pragma unroll
    for (int o = 16; o; o >>= 1) {
        float om = __shfl_xor_sync(0xffffffffu, m, o);
        float os = __shfl_xor_sync(0xffffffffu, s, o);
        float M = fmaxf(m, om);
        s = s * __expf(m - M) + os * __expf(om - M);
        m = M;
    }
    if ((t & 31) == 0) { rm[t >> 5] = m; rs[t >> 5] = s; }
    __syncthreads();
    if (t < 8) {
        m = rm[t]; s = rs[t];
        #pragma unroll
        for (int o = 4; o; o >>= 1) {
            float om = __shfl_xor_sync(0xffu, m, o);
            float os = __shfl_xor_sync(0xffu, s, o);
            float M = fmaxf(m, om);
            s = s * __expf(m - M) + os * __expf(om - M);
            m = M;
        }
        if (t == 0) g_lse = m + logf(s);
    }
}

// ---------------- K7: normalize log-probs ----------------------------------
__global__ void __launch_bounds__(256)
k_norm(float* __restrict__ out) {
    int v = blockIdx.x * blockDim.x + threadIdx.x;
    if (v < V) out[v] -= g_lse;
}

// ---------------- launch ----------------------------------------------------
extern "C" void kernel_launch(void* const* d_in, const int* in_sizes, int n_in,
                              void* d_out, int out_size) {
    const int*   ids     = (const int*)d_in[0];
    const float* hidden  = (const float*)d_in[1];
    const float* enc     = (const float*)d_in[2];
    const float* emb     = (const float*)d_in[3];
    const float* attn_w  = (const float*)d_in[4];
    const float* attn_b  = (const float*)d_in[5];
    const float* comb_w  = (const float*)d_in[6];
    const float* comb_b  = (const float*)d_in[7];
    const float* w_ih    = (const float*)d_in[8];
    const float* w_hh    = (const float*)d_in[9];
    const float* b_ih    = (const float*)d_in[10];
    const float* b_hh    = (const float*)d_in[11];
    const float* out_w   = (const float*)d_in[12];
    const float* out_b   = (const float*)d_in[13];
    float* out = (float*)d_out;

    k_scores<<<L, 256>>>(ids, hidden, emb, attn_w, attn_b);
    k_attn<<<8, 128>>>(enc, out);
    k_comb<<<H / 4, 256>>>(comb_w, comb_b);
    k_gates<<<3072, 256>>>(w_ih, w_hh, 0);
    k_combine<<<8, 128>>>(b_ih, b_hh, out, 0);
    k_gates<<<3072, 256>>>(w_ih, w_hh, 1);
    k_combine<<<8, 128>>>(b_ih, b_hh, out, 1);
    k_out<<<NBLK, 256>>>(out_w, out_b, out);
    k_lse<<<1, 256>>>();
    k_norm<<<(V + 255) / 256, 256>>>(out);
}

// round 10
// speedup vs baseline: 1.1018x; 1.1018x over previous
#include <cuda_runtime.h>
#include <cuda_bf16.h>

#define H 1024
#define L 50
#define V 50257
#define NBLK ((V + 7) / 8)   // 6283 blocks for the big matvec

// ---------------- scratch (device globals; no allocation allowed) ----------
__device__ float g_emb[H];        // embedded row
__device__ float g_scores[L];     // attention logits
__device__ float g_cat2[2 * H];   // [embedded | attn_applied]
__device__ float g_x0[H];         // relu(comb out)  = GRU cell-0 input
__device__ float g_h0[H];         // initial hidden
__device__ float g_x1[H];         // relu(h1)        = GRU cell-1 input
__device__ float g_h1[H];         // h after cell 1
__device__ float g_h2[H];         // h after cell 2 (final)
__device__ float g_dp[2 * 6 * H]; // half-row gate partials [half][c][i]
__device__ float g_pm[NBLK + 64]; // per-block partial max
__device__ float g_ps[NBLK + 64]; // per-block partial sum-exp
__device__ float g_lse;

// ---------------- K0: attention scores (one block per l) -------------------
__global__ void __launch_bounds__(256)
k_scores(const int* __restrict__ ids,
         const float* __restrict__ hidden,
         const float* __restrict__ emb,
         const float* __restrict__ attn_w,
         const float* __restrict__ attn_b) {
    int l = blockIdx.x;
    int row = ids[0];
    const float* er = emb + (size_t)row * H;

    if (l == 0) {
        for (int i = threadIdx.x; i < H; i += blockDim.x) {
            g_emb[i] = er[i];
            g_h0[i]  = hidden[i];
        }
    }

    const float* w = attn_w + (size_t)l * 2 * H;
    float acc = 0.f;
    for (int j = threadIdx.x; j < H; j += blockDim.x)
        acc += w[j] * er[j] + w[H + j] * hidden[j];

    __shared__ float red[8];
    #pragma unroll
    for (int o = 16; o; o >>= 1) acc += __shfl_down_sync(0xffffffffu, acc, o);
    if ((threadIdx.x & 31) == 0) red[threadIdx.x >> 5] = acc;
    __syncthreads();
    if (threadIdx.x < 8) {
        float v = red[threadIdx.x];
        #pragma unroll
        for (int o = 4; o; o >>= 1) v += __shfl_down_sync(0xffu, v, o);
        if (threadIdx.x == 0) g_scores[l] = v + attn_b[l];
    }
}

// ---------------- K1: softmax + attn_applied + concat (8 blocks) -----------
__global__ void __launch_bounds__(128)
k_attn(const float* __restrict__ enc, float* __restrict__ out) {
    __shared__ float aw[64];
    int t = threadIdx.x;
    if (t < 64) aw[t] = (t < L) ? g_scores[t] : -1e30f;
    __syncthreads();
    if (t < 32) {
        float a = aw[t], b = aw[t + 32];
        float m = fmaxf(a, b);
        #pragma unroll
        for (int o = 16; o; o >>= 1) m = fmaxf(m, __shfl_xor_sync(0xffffffffu, m, o));
        float e1 = (t < L) ? __expf(a - m) : 0.f;
        float e2 = (t + 32 < L) ? __expf(b - m) : 0.f;
        float s = e1 + e2;
        #pragma unroll
        for (int o = 16; o; o >>= 1) s += __shfl_xor_sync(0xffffffffu, s, o);
        float inv = 1.f / s;
        aw[t] = e1 * inv;
        aw[t + 32] = e2 * inv;
    }
    __syncthreads();
    if (blockIdx.x == 0 && t < L) out[V + H + t] = aw[t];   // attn_weights
    int i = blockIdx.x * 128 + t;                           // column slice
    float acc = 0.f;
    #pragma unroll 10
    for (int l = 0; l < L; l++) acc += aw[l] * enc[l * H + i];
    g_cat2[H + i] = acc;
    g_cat2[i] = g_emb[i];
}

// ---------------- K2: comb matvec (2 warps per row, grid=256) --------------
// Writes relu(comb) straight into g_x0 (GRU cell-0 input).
__global__ void __launch_bounds__(256)
k_comb(const float* __restrict__ comb_w,
       const float* __restrict__ comb_b) {
    __shared__ float sc[2 * H];
    __shared__ float part[8];
    for (int i = threadIdx.x; i < 2 * H; i += 256) sc[i] = g_cat2[i];
    __syncthreads();
    int warp = threadIdx.x >> 5, lane = threadIdx.x & 31;
    int row = blockIdx.x * 4 + (warp >> 1);
    int half = warp & 1;
    const float4* w = (const float4*)(comb_w + (size_t)row * 2 * H + half * H);
    float acc = 0.f;
    #pragma unroll
    for (int k = 0; k < 8; k++) {
        int m = lane + k * 32;
        float4 a = w[m];
        int j = half * H + m * 4;
        acc += a.x * sc[j] + a.y * sc[j + 1] + a.z * sc[j + 2] + a.w * sc[j + 3];
    }
    #pragma unroll
    for (int o = 16; o; o >>= 1) acc += __shfl_down_sync(0xffffffffu, acc, o);
    if (lane == 0) part[warp] = acc;
    __syncthreads();
    if (threadIdx.x < 4) {
        int r2 = blockIdx.x * 4 + threadIdx.x;
        float v = part[2 * threadIdx.x] + part[2 * threadIdx.x + 1] + comb_b[r2];
        g_x0[r2] = fmaxf(v, 0.f);       // pre-relu'd GRU input
    }
}

// ---------------- K3: GRU gate half-dots — NO smem, NO barrier -------------
// One warp per (matrix, gate, row, half): 12288 warps / 1536 blocks.
// Weights: 4 front-batched LDG.128. Vector: 4 LDG.128 that L1-hit after the
// SM warms (4 KB vector resident in 228 KB L1). Pure independent strands.
__global__ void __launch_bounds__(256)
k_gates(const float* __restrict__ w_ih, const float* __restrict__ w_hh,
        int cell) {
    int warp = threadIdx.x >> 5, lane = threadIdx.x & 31;
    int id = blockIdx.x * 8 + warp;          // 0..12287
    int half = id & 1;
    int i = (id >> 1) & (H - 1);             // output row
    int c = id >> 11;                        // 0..5
    int gate = c >> 1;
    const float* wmat = (c & 1) ? w_hh : w_ih;
    const float4* w = (const float4*)(wmat + (size_t)(gate * H + i) * H) + half * 128;

    // 4 front-batched weight loads (DRAM stream)
    float4 r0 = w[lane];
    float4 r1 = w[lane + 32];
    float4 r2 = w[lane + 64];
    float4 r3 = w[lane + 96];

    // vector loads (L1-resident after first touch per SM)
    const float* vecf = (c & 1) ? ((cell == 0) ? g_h0 : g_h1)
                                : ((cell == 0) ? g_x0 : g_x1);
    const float4* v = (const float4*)vecf + half * 128;
    float4 v0 = v[lane];
    float4 v1 = v[lane + 32];
    float4 v2 = v[lane + 64];
    float4 v3 = v[lane + 96];

    float acc = r0.x * v0.x + r0.y * v0.y + r0.z * v0.z + r0.w * v0.w
              + r1.x * v1.x + r1.y * v1.y + r1.z * v1.z + r1.w * v1.w
              + r2.x * v2.x + r2.y * v2.y + r2.z * v2.z + r2.w * v2.w
              + r3.x * v3.x + r3.y * v3.y + r3.z * v3.z + r3.w * v3.w;
    #pragma unroll
    for (int o = 16; o; o >>= 1) acc += __shfl_down_sync(0xffffffffu, acc, o);
    if (lane == 0) g_dp[half * 6 * H + c * H + i] = acc;
}

// ---------------- K4: GRU combine: sum halves + biases + nonlinearity ------
__global__ void __launch_bounds__(128)
k_combine(const float* __restrict__ b_ih, const float* __restrict__ b_hh,
          float* __restrict__ out, int cell) {
    int i = blockIdx.x * 128 + threadIdx.x;
    float hold = (cell == 0) ? g_h0[i] : g_h1[i];
    float d[6];
    #pragma unroll
    for (int c = 0; c < 6; c++) {
        float s = g_dp[c * H + i] + g_dp[6 * H + c * H + i];
        int gate = c >> 1;
        s += (c & 1) ? b_hh[gate * H + i] : b_ih[gate * H + i];
        d[c] = s;
    }
    float r = 1.f / (1.f + __expf(-(d[0] + d[1])));
    float z = 1.f / (1.f + __expf(-(d[2] + d[3])));
    float n = tanhf(d[4] + r * d[5]);
    float h = (1.f - z) * n + z * hold;
    if (cell == 0) {
        g_h1[i] = h;
        g_x1[i] = fmaxf(h, 0.f);        // pre-relu'd cell-1 input
    } else {
        g_h2[i] = h;
        out[V + i] = h;                 // hidden output
    }
}

// ---------------- K5: big matvec out_w @ h — no smem vector stage ----------
__global__ void __launch_bounds__(256)
k_out(const float* __restrict__ out_w,
      const float* __restrict__ out_b,
      float* __restrict__ out) {
    __shared__ float sm[8];
    int warp = threadIdx.x >> 5, lane = threadIdx.x & 31;
    int row = blockIdx.x * 8 + warp;
    float logit = -1e30f;
    if (row < V) {
        const float4* w = (const float4*)(out_w + (size_t)row * H);
        const float4* v = (const float4*)g_h2;
        float acc = 0.f;
        #pragma unroll
        for (int k = 0; k < 8; k++) {
            int m = lane + k * 32;
            float4 a = __ldcs(w + m);   // stream weights: don't pollute L2
            float4 b = v[m];            // L1-resident vector
            acc += a.x * b.x + a.y * b.y + a.z * b.z + a.w * b.w;
        }
        #pragma unroll
        for (int o = 16; o; o >>= 1) acc += __shfl_down_sync(0xffffffffu, acc, o);
        if (lane == 0) {
            logit = acc + out_b[row];
            out[row] = logit;
        }
    }
    if (lane == 0) sm[warp] = logit;
    __syncthreads();
    if (threadIdx.x == 0) {
        float m = -1e30f;
        #pragma unroll
        for (int k = 0; k < 8; k++) m = fmaxf(m, sm[k]);
        float s = 0.f;
        #pragma unroll
        for (int k = 0; k < 8; k++) s += __expf(sm[k] - m);
        g_pm[blockIdx.x] = m;
        g_ps[blockIdx.x] = s;
    }
}

// ---------------- K6: combine partials -> lse ------------------------------
__global__ void __launch_bounds__(256)
k_lse() {
    int t = threadIdx.x;
    float m = -1e30f, s = 0.f;
    for (int b = t; b < NBLK; b += 256) {
        float bm = g_pm[b], bs = g_ps[b];
        if (bm > m) { s = s * __expf(m - bm) + bs; m = bm; }
        else        { s += bs * __expf(bm - m); }
    }
    __shared__ float rm[8], rs[8];
    #pragma unroll
    for (int o = 16; o; o >>= 1) {
        float om = __shfl_xor_sync(0xffffffffu, m, o);
        float os = __shfl_xor_sync(0xffffffffu, s, o);
        float M = fmaxf(m, om);
        s = s * __expf(m - M) + os * __expf(om - M);
        m = M;
    }
    if ((t & 31) == 0) { rm[t >> 5] = m; rs[t >> 5] = s; }
    __syncthreads();
    if (t < 8) {
        m = rm[t]; s = rs[t];
        #pragma unroll
        for (int o = 4; o; o >>= 1) {
            float om = __shfl_xor_sync(0xffu, m, o);
            float os = __shfl_xor_sync(0xffu, s, o);
            float M = fmaxf(m, om);
            s = s * __expf(m - M) + os * __expf(om - M);
            m = M;
        }
        if (t == 0) g_lse = m + logf(s);
    }
}

// ---------------- K7: normalize log-probs ----------------------------------
__global__ void __launch_bounds__(256)
k_norm(float* __restrict__ out) {
    int v = blockIdx.x * blockDim.x + threadIdx.x;
    if (v < V) out[v] -= g_lse;
}

// ---------------- launch ----------------------------------------------------
extern "C" void kernel_launch(void* const* d_in, const int* in_sizes, int n_in,
                              void* d_out, int out_size) {
    const int*   ids     = (const int*)d_in[0];
    const float* hidden  = (const float*)d_in[1];
    const float* enc     = (const float*)d_in[2];
    const float* emb     = (const float*)d_in[3];
    const float* attn_w  = (const float*)d_in[4];
    const float* attn_b  = (const float*)d_in[5];
    const float* comb_w  = (const float*)d_in[6];
    const float* comb_b  = (const float*)d_in[7];
    const float* w_ih    = (const float*)d_in[8];
    const float* w_hh    = (const float*)d_in[9];
    const float* b_ih    = (const float*)d_in[10];
    const float* b_hh    = (const float*)d_in[11];
    const float* out_w   = (const float*)d_in[12];
    const float* out_b   = (const float*)d_in[13];
    float* out = (float*)d_out;

    k_scores<<<L, 256>>>(ids, hidden, emb, attn_w, attn_b);
    k_attn<<<8, 128>>>(enc, out);
    k_comb<<<H / 4, 256>>>(comb_w, comb_b);
    k_gates<<<1536, 256>>>(w_ih, w_hh, 0);
    k_combine<<<8, 128>>>(b_ih, b_hh, out, 0);
    k_gates<<<1536, 256>>>(w_ih, w_hh, 1);
    k_combine<<<8, 128>>>(b_ih, b_hh, out, 1);
    k_out<<<NBLK, 256>>>(out_w, out_b, out);
    k_lse<<<1, 256>>>();
    k_norm<<<(V + 255) / 256, 256>>>(out);
}